// round 16
// baseline (speedup 1.0000x reference)
#include <cuda_runtime.h>
#include <cuda_bf16.h>
#include <math.h>
#include <stdint.h>

#define C_CLUST 10
#define D_IN    1024
#define D_H     512
#define D_ATT   256
#define N_CLS   4
#define N_MAX   10000
#define NPAD    128

#define KC 64
#define ROWB 144                            // smem row stride bytes (72 bf16)
#define MT   64                             // CTA tile rows
#define A_BYTES (MT * ROWB)                 // 9216
#define B_BYTES (128 * ROWB)                // 18432
#define STAGE_BYTES (A_BYTES + B_BYTES)     // 27648
#define SMEM_SZ (2 * STAGE_BYTES)           // 55296 (>= conv 64x129x4=33KB, >= epilogue 4KB)

#define NCONV_W1 640                        // 10 * (1024/64)*(512/128)
#define NCONV_W2 320                        // 10 * (512/64)*(512/128)
#define CW1_PER  64
#define CW2_PER  32
#define GROWS    32
#define NE1T     160                        // E1: (cluster, 32-col block)
#define NE2T     80                         // E2: (cluster, 32-attcol block)
#define NE3      8
#define MBMAX    160                        // max 64-row m-blocks per cluster

// ---------------- scratch ----------------
__device__ int   g_count[C_CLUST];
__device__ int   g_off[C_CLUST];
__device__ int   g_cursor[C_CLUST];
__device__ int   g_g1s[C_CLUST + 1];
__device__ int   g_g2s[C_CLUST + 1];
__device__ int   g_ng;
__device__ int   g_tb[8];
__device__ int   g_ntask;
__device__ int   g_task;
__device__ int   g_gather_done;
__device__ int   g_cw1c[C_CLUST];
__device__ int   g_cw2c[C_CLUST];
__device__ int   g_g1_mb[C_CLUST * MBMAX];
__device__ int   g_g2_done[C_CLUST];
__device__ int   g_e1c[C_CLUST];
__device__ int   g_e2, g_e3;
__device__ __nv_bfloat16 g_Xg[(size_t)(N_MAX + NPAD) * D_IN];
__device__ __nv_bfloat16 g_H1[(size_t)(N_MAX + NPAD) * D_H];
__device__ __nv_bfloat16 g_W1t[(size_t)C_CLUST * D_H * D_IN];
__device__ __nv_bfloat16 g_W2t[(size_t)C_CLUST * D_H * D_H];
__device__ float g_pool[C_CLUST * D_H];
__device__ float g_hbuf[C_CLUST * D_H];
__device__ float g_AccA[C_CLUST];
__device__ float g_hr[D_ATT];

__device__ __forceinline__ int detect64(const void* cid) {
    const int* p = (const int*)cid;
    int allz = 1;
#pragma unroll
    for (int i = 1; i < 32; i += 2) if (p[i] != 0) allz = 0;
    return allz;
}
__device__ __forceinline__ int get_cid(const void* cid, int n, int is64) {
    if (is64) return (int)((const long long*)cid)[n];
    return ((const int*)cid)[n];
}
__device__ __forceinline__ uint32_t smem_u32(const void* p) {
    uint32_t a;
    asm("{ .reg .u64 t; cvta.to.shared.u64 t, %1; cvt.u32.u64 %0, t; }" : "=r"(a) : "l"(p));
    return a;
}
__device__ __forceinline__ void cp16(uint32_t smem, const void* gmem) {
    asm volatile("cp.async.cg.shared.global [%0], [%1], 16;" :: "r"(smem), "l"(gmem));
}
__device__ __forceinline__ void ldsm4(uint32_t& r0, uint32_t& r1, uint32_t& r2, uint32_t& r3,
                                      uint32_t addr) {
    asm volatile("ldmatrix.sync.aligned.m8n8.x4.shared.b16 {%0,%1,%2,%3}, [%4];"
                 : "=r"(r0), "=r"(r1), "=r"(r2), "=r"(r3) : "r"(addr));
}
__device__ __forceinline__ void mma_bf16(float c[4], uint32_t a0, uint32_t a1, uint32_t a2,
                                         uint32_t a3, uint32_t b0, uint32_t b1) {
    asm volatile(
        "mma.sync.aligned.m16n8k16.row.col.f32.bf16.bf16.f32 "
        "{%0,%1,%2,%3}, {%4,%5,%6,%7}, {%8,%9}, {%0,%1,%2,%3};\n"
        : "+f"(c[0]), "+f"(c[1]), "+f"(c[2]), "+f"(c[3])
        : "r"(a0), "r"(a1), "r"(a2), "r"(a3), "r"(b0), "r"(b1));
}
__device__ __forceinline__ int ldacq(const int* p) {
    int v; asm volatile("ld.acquire.gpu.s32 %0, [%1];" : "=r"(v) : "l"(p)); return v;
}
#define SPIN_WAIT(cond) do {                      \
    int _sl = 64;                                 \
    while (cond) {                                \
        __nanosleep(_sl);                         \
        if (_sl < 512) _sl <<= 1;                 \
    }                                             \
} while (0)

// ---------------- prep kernels ----------------
__global__ void k_reset() {
    int t = threadIdx.x;   // 512
    for (int i = t; i < C_CLUST * D_H; i += 512) g_pool[i] = 0.f;
    for (int i = t; i < C_CLUST * MBMAX; i += 512) g_g1_mb[i] = 0;
    if (t < C_CLUST) {
        g_count[t] = 0; g_cursor[t] = 0; g_g2_done[t] = 0;
        g_cw1c[t] = 0; g_cw2c[t] = 0;
        g_e1c[t] = 0; g_AccA[t] = 0.f;
    }
    if (t == 0) {
        g_task = 0; g_gather_done = 0; g_e2 = 0; g_e3 = 0;
    }
}

__global__ void k_count(const void* __restrict__ cid, int n) {
    __shared__ int s[C_CLUST];
    int t = threadIdx.x;
    int is64 = detect64(cid);
    if (t < C_CLUST) s[t] = 0;
    __syncthreads();
    int i = blockIdx.x * blockDim.x + t;
    if (i < n) atomicAdd(&s[get_cid(cid, i, is64)], 1);
    __syncthreads();
    if (t < C_CLUST && s[t]) atomicAdd(&g_count[t], s[t]);
}

__global__ void k_offsets(int n) {
    if (threadIdx.x == 0) {
        int o = 0, g1 = 0, g2 = 0;
        for (int c = 0; c < C_CLUST; c++) {
            g_off[c] = o; o += g_count[c];
            int mt = (g_count[c] + MT - 1) / MT;
            g_g1s[c] = g1; g1 += 4 * mt;
            g_g2s[c] = g2; g2 += 4 * mt;
        }
        g_g1s[C_CLUST] = g1;
        g_g2s[C_CLUST] = g2;
        int ng = (n + GROWS - 1) / GROWS;
        g_ng = ng;
        g_tb[0] = ng;
        g_tb[1] = g_tb[0] + NCONV_W1;
        g_tb[2] = g_tb[1] + g1;
        g_tb[3] = g_tb[2] + NCONV_W2;
        g_tb[4] = g_tb[3] + g2;
        g_tb[5] = g_tb[4] + NE1T;
        g_tb[6] = g_tb[5] + NE2T;
        g_tb[7] = g_tb[6] + NE3;
        g_ntask = g_tb[7] + 1;
    }
}

// ---------------- gather task ----------------
__device__ void gather_task(const float* __restrict__ x, const void* __restrict__ cid,
                            int n, int base, char* dsm, int tid) {
    int* slot = (int*)dsm;
    if (tid < GROWS) {
        int p = base + tid;
        int s = -1;
        if (p < n) {
            int is64 = detect64(cid);
            int c = get_cid(cid, p, is64);
            s = g_off[c] + atomicAdd(&g_cursor[c], 1);
        }
        slot[tid] = s;
    }
    __syncthreads();
    int r = tid >> 3, q = tid & 7;
    int p = base + r;
    if (p < n) {
        int dst = slot[r];
        const float4* src = (const float4*)(x + (size_t)p * D_IN);
        uint2* d = (uint2*)(g_Xg + (size_t)dst * D_IN);
#pragma unroll 8
        for (int i = 0; i < 32; i++) {
            float4 v = src[i * 8 + q];
            __nv_bfloat162 lo = __floats2bfloat162_rn(v.x, v.y);
            __nv_bfloat162 hi = __floats2bfloat162_rn(v.z, v.w);
            uint2 u;
            u.x = *(uint32_t*)&lo;
            u.y = *(uint32_t*)&hi;
            d[i * 8 + q] = u;
        }
    }
    __threadfence();
    __syncthreads();
    if (tid == 0) atomicAdd(&g_gather_done, 1);
    __syncthreads();
}

// ---------------- conv tile: 64x128 transpose fp32 -> bf16 (33KB smem) ----------------
__device__ void conv_tile(const float* __restrict__ src, __nv_bfloat16* __restrict__ dst,
                          int R, int C, int r0, int c0, float* sm, int tid) {
    int r = tid >> 2;                        // 0..63
    int cb = (tid & 3) * 32;                 // 4 threads/row, 32 floats each
    const float* s = src + (size_t)(r0 + r) * C + c0 + cb;
#pragma unroll
    for (int q = 0; q < 8; q++) {
        float4 v = *(const float4*)(s + q * 4);
        float* d = sm + r * 129 + cb + q * 4;
        d[0] = v.x; d[1] = v.y; d[2] = v.z; d[3] = v.w;
    }
    __syncthreads();
    // write transposed: 128 cols x 64 rows; uint2 = 4 rows; 2048 uint2 / 256 thr = 8 each
#pragma unroll
    for (int q = 0; q < 8; q++) {
        int lin = q * 256 + tid;
        int j = lin >> 4;                    // 0..127 col
        int i4 = (lin & 15) * 4;             // 0..60 row
        float a0 = sm[(i4 + 0) * 129 + j];
        float a1 = sm[(i4 + 1) * 129 + j];
        float a2 = sm[(i4 + 2) * 129 + j];
        float a3 = sm[(i4 + 3) * 129 + j];
        __nv_bfloat162 lo = __floats2bfloat162_rn(a0, a1);
        __nv_bfloat162 hi = __floats2bfloat162_rn(a2, a3);
        uint2 u;
        u.x = *(uint32_t*)&lo;
        u.y = *(uint32_t*)&hi;
        *(uint2*)(dst + (size_t)(c0 + j) * R + r0 + i4) = u;
    }
    __syncthreads();
}

// ---------------- GEMM tile: CTA 64x128, warp 32x32, 2-stage cp.async ----------------
template <bool POOL>
__device__ __forceinline__ void gemm_tile(
    const __nv_bfloat16* __restrict__ Aglob, const __nv_bfloat16* __restrict__ Wc,
    const float* __restrict__ bias_c, float* __restrict__ pool_c,
    int K, int M, int seg, int m0, int n0, char* dsm, float* s_col, int tid) {

    uint32_t sbase = smem_u32(dsm);
    int lane = tid & 31;
    int w = tid >> 5;
    int wm = w & 1;                          // 2 row-halves of 32
    int wn = w >> 1;                         // 4 col-quarters of 32
    int g = lane >> 2;
    int tig = lane & 3;
    int l7 = lane & 7, l8 = (lane >> 3) & 1, l16 = lane >> 4;

    float acc[2][4][4];
#pragma unroll
    for (int im = 0; im < 2; im++)
#pragma unroll
        for (int in = 0; in < 4; in++)
#pragma unroll
            for (int q = 0; q < 4; q++) acc[im][in][q] = 0.f;

    // cp.async mappings: A 64 rows x 128B (4 thr/row, 2x16B each); B 128 rows (2 thr/row, 4x16B)
    int ar = tid >> 2;
    int aseg = (tid & 3) * 2;                // 16B units within row
    const __nv_bfloat16* Arow = Aglob + (size_t)(seg + m0 + ar) * K + aseg * 8;
    uint32_t a_sm = ar * ROWB + aseg * 16;
    int br = tid >> 1;
    int bseg = (tid & 1) * 4;
    const __nv_bfloat16* Brow = Wc + (size_t)(n0 + br) * K + bseg * 8;
    uint32_t b_sm = A_BYTES + br * ROWB + bseg * 16;

    uint32_t a_frag = (uint32_t)(wm * 32 + l7 + 8 * l8) * ROWB + 16 * l16;
    uint32_t b_frag = A_BYTES + (uint32_t)(wn * 32 + l7 + 8 * l8) * ROWB + 16 * l16;

    int nch = K / KC;
    {
        uint32_t st = sbase;
#pragma unroll
        for (int q = 0; q < 2; q++) cp16(st + a_sm + q * 16, Arow + q * 8);
#pragma unroll
        for (int q = 0; q < 4; q++) cp16(st + b_sm + q * 16, Brow + q * 8);
        asm volatile("cp.async.commit_group;" ::: "memory");
    }

    for (int c = 0; c < nch; c++) {
        if (c + 1 < nch) {
            uint32_t st = sbase + ((c + 1) & 1) * STAGE_BYTES;
            const __nv_bfloat16* ap = Arow + (c + 1) * KC;
            const __nv_bfloat16* bp = Brow + (c + 1) * KC;
#pragma unroll
            for (int q = 0; q < 2; q++) cp16(st + a_sm + q * 16, ap + q * 8);
#pragma unroll
            for (int q = 0; q < 4; q++) cp16(st + b_sm + q * 16, bp + q * 8);
            asm volatile("cp.async.commit_group;" ::: "memory");
            asm volatile("cp.async.wait_group 1;" ::: "memory");
        } else {
            asm volatile("cp.async.wait_group 0;" ::: "memory");
        }
        __syncthreads();

        uint32_t stb = sbase + (c & 1) * STAGE_BYTES;
#pragma unroll
        for (int ks = 0; ks < 4; ks++) {
            uint32_t koff = ks * 32;
            uint32_t bfr[2][4];
#pragma unroll
            for (int p = 0; p < 2; p++)
                ldsm4(bfr[p][0], bfr[p][1], bfr[p][2], bfr[p][3],
                      stb + b_frag + p * (16 * ROWB) + koff);
            uint32_t afr[2][4];
#pragma unroll
            for (int im = 0; im < 2; im++)
                ldsm4(afr[im][0], afr[im][1], afr[im][2], afr[im][3],
                      stb + a_frag + im * (16 * ROWB) + koff);
#pragma unroll
            for (int im = 0; im < 2; im++) {
#pragma unroll
                for (int p = 0; p < 2; p++) {
                    mma_bf16(acc[im][2 * p],     afr[im][0], afr[im][1], afr[im][2], afr[im][3],
                             bfr[p][0], bfr[p][2]);
                    mma_bf16(acc[im][2 * p + 1], afr[im][0], afr[im][1], afr[im][2], afr[im][3],
                             bfr[p][1], bfr[p][3]);
                }
            }
        }
        __syncthreads();
    }

    const float* bp = bias_c + n0;

    if (!POOL) {
#pragma unroll
        for (int im = 0; im < 2; im++) {
            int rg = m0 + wm * 32 + im * 16 + g;
            int rg8 = rg + 8;
#pragma unroll
            for (int in = 0; in < 4; in++) {
                int col = wn * 32 + in * 8 + 2 * tig;
                float b0v = bp[col], b1v = bp[col + 1];
                if (rg < M) {
                    __nv_bfloat162 v = __floats2bfloat162_rn(
                        fmaxf(acc[im][in][0] + b0v, 0.f), fmaxf(acc[im][in][1] + b1v, 0.f));
                    *(__nv_bfloat162*)&g_H1[(size_t)(seg + rg) * D_H + n0 + col] = v;
                }
                if (rg8 < M) {
                    __nv_bfloat162 v = __floats2bfloat162_rn(
                        fmaxf(acc[im][in][2] + b0v, 0.f), fmaxf(acc[im][in][3] + b1v, 0.f));
                    *(__nv_bfloat162*)&g_H1[(size_t)(seg + rg8) * D_H + n0 + col] = v;
                }
            }
        }
    } else {
        if (tid < 128) s_col[tid] = 0.f;
        __syncthreads();
#pragma unroll
        for (int in = 0; in < 4; in++) {
            int col = wn * 32 + in * 8 + 2 * tig;
            float b0v = bp[col], b1v = bp[col + 1];
            float px = 0.f, py = 0.f;
#pragma unroll
            for (int im = 0; im < 2; im++) {
                int rg = m0 + wm * 32 + im * 16 + g;
                if (rg < M) {
                    px += fmaxf(acc[im][in][0] + b0v, 0.f);
                    py += fmaxf(acc[im][in][1] + b1v, 0.f);
                }
                if (rg + 8 < M) {
                    px += fmaxf(acc[im][in][2] + b0v, 0.f);
                    py += fmaxf(acc[im][in][3] + b1v, 0.f);
                }
            }
            atomicAdd(&s_col[col], px);
            atomicAdd(&s_col[col + 1], py);
        }
        __syncthreads();
        if (tid < 128) atomicAdd(&pool_c[n0 + tid], s_col[tid]);
    }
}

// ---------------- E1: fc, one (cluster, 32-col) task ----------------
__device__ void e1_task(int c, int i, const float* __restrict__ Wfc,
                        const float* __restrict__ bfc, char* dsm, int tid) {
    float* ph = (float*)dsm;
    float* s_p = ph + D_H;
    int j0 = i * 32;
    int j = tid & 31, ks = tid >> 5;
    float inv = 1.f / (float)max(g_count[c], 1);
    for (int q = tid; q < D_H; q += 256) ph[q] = g_pool[c * D_H + q] * inv;
    __syncthreads();
    float p = 0.f;
#pragma unroll 8
    for (int k = ks * 64; k < ks * 64 + 64; k++)
        p += ph[k] * Wfc[k * D_H + j0 + j];
    s_p[ks * 32 + j] = p;
    __syncthreads();
    if (tid < 32) {
        float s = 0.f;
#pragma unroll
        for (int q = 0; q < 8; q++) s += s_p[q * 32 + tid];
        g_hbuf[c * D_H + j0 + tid] = fmaxf(s + bfc[j0 + tid], 0.f);
    }
    __threadfence();
    __syncthreads();
    if (tid == 0) atomicAdd(&g_e1c[c], 1);
    __syncthreads();
}

// ---------------- E2: gated attention, one (cluster, 32-attcol) task ----------------
__device__ void e2_task(int c, int i, const float* __restrict__ Wa, const float* __restrict__ ba,
                        const float* __restrict__ Wb, const float* __restrict__ bb,
                        const float* __restrict__ Wcs, char* dsm, int tid) {
    float* hc = (float*)dsm;
    float* s_sa = hc + D_H;
    float* s_sb = s_sa + 256;
    int col0 = i * 32;
    int col = tid & 31, ks = tid >> 5;
    for (int q = tid; q < D_H; q += 256) hc[q] = g_hbuf[c * D_H + q];
    __syncthreads();
    float sa = 0.f, sb = 0.f;
#pragma unroll 8
    for (int k = ks * 64; k < ks * 64 + 64; k++) {
        float hv = hc[k];
        sa += hv * Wa[k * D_ATT + col0 + col];
        sb += hv * Wb[k * D_ATT + col0 + col];
    }
    s_sa[ks * 32 + col] = sa;
    s_sb[ks * 32 + col] = sb;
    __syncthreads();
    if (tid < 32) {
        float ta = 0.f, tb = 0.f;
#pragma unroll
        for (int q = 0; q < 8; q++) { ta += s_sa[q * 32 + tid]; tb += s_sb[q * 32 + tid]; }
        float gate = tanhf(ta + ba[col0 + tid]) *
                     (1.f / (1.f + expf(-(tb + bb[col0 + tid]))));
        float part = gate * Wcs[col0 + tid];
#pragma unroll
        for (int off = 16; off > 0; off >>= 1)
            part += __shfl_down_sync(0xffffffff, part, off);
        if (tid == 0) atomicAdd(&g_AccA[c], part);
    }
    __threadfence();
    __syncthreads();
    if (tid == 0) atomicAdd(&g_e2, 1);
    __syncthreads();
}

// ---------------- E3: softmax + h_path + rho (32-col block) ----------------
__device__ void e3_task(int i, const float* __restrict__ bcs,
                        const float* __restrict__ Wr, const float* __restrict__ br,
                        char* dsm, int tid) {
    float* A = (float*)dsm;
    float* hp = A + 16;
    float* s_p = hp + D_H;
    int j0 = i * 32;
    if (tid == 0) {
        float m = -1e30f;
        float araw[C_CLUST];
        for (int c = 0; c < C_CLUST; c++) { araw[c] = g_AccA[c] + bcs[0]; m = fmaxf(m, araw[c]); }
        float s = 0.f;
        for (int c = 0; c < C_CLUST; c++) { A[c] = expf(araw[c] - m); s += A[c]; }
        float inv = 1.f / s;
        for (int c = 0; c < C_CLUST; c++) A[c] *= inv;
    }
    __syncthreads();
    for (int k = tid; k < D_H; k += 256) {
        float s = 0.f;
#pragma unroll
        for (int c = 0; c < C_CLUST; c++) s += A[c] * g_hbuf[c * D_H + k];
        hp[k] = s;
    }
    __syncthreads();
    int j = tid & 31, ks = tid >> 5;
    float p = 0.f;
#pragma unroll 8
    for (int k = ks * 64; k < ks * 64 + 64; k++)
        p += hp[k] * Wr[k * D_ATT + j0 + j];
    s_p[ks * 32 + j] = p;
    __syncthreads();
    if (tid < 32) {
        float s = 0.f;
#pragma unroll
        for (int q = 0; q < 8; q++) s += s_p[q * 32 + tid];
        g_hr[j0 + tid] = fmaxf(s + br[j0 + tid], 0.f);
    }
    __threadfence();
    __syncthreads();
    if (tid == 0) atomicAdd(&g_e3, 1);
    __syncthreads();
}

// ---------------- E4: classifier + softmax + argmax + output ----------------
__device__ void e4_task(const float* __restrict__ Wcls, const float* __restrict__ bcls,
                        float* __restrict__ out, int out_size, char* dsm, int tid) {
    float* hr = (float*)dsm;
    float* red = hr + 256;
    float* lg = red + 256;
    hr[tid] = g_hr[tid];
    __syncthreads();
    for (int i = 0; i < N_CLS; i++) {
        red[tid] = hr[tid] * Wcls[tid * N_CLS + i];
        __syncthreads();
        for (int s = 128; s > 0; s >>= 1) {
            if (tid < s) red[tid] += red[tid + s];
            __syncthreads();
        }
        if (tid == 0) lg[i] = red[0] + bcls[i];
        __syncthreads();
    }
    if (tid == 0) {
        float m = lg[0];
        int am = 0;
        for (int i = 1; i < N_CLS; i++) if (lg[i] > m) { m = lg[i]; am = i; }
        float e[N_CLS], s = 0.f;
        for (int i = 0; i < N_CLS; i++) { e[i] = expf(lg[i] - m); s += e[i]; }
        float vals[9];
        for (int i = 0; i < N_CLS; i++) vals[i] = lg[i];
        for (int i = 0; i < N_CLS; i++) vals[4 + i] = e[i] / s;
        vals[8] = (float)am;
        for (int i = 0; i < out_size; i++) out[i] = (i < 9) ? vals[i] : 0.f;
    }
    __syncthreads();
}

// ---------------- persistent mega kernel ----------------
__global__ void __launch_bounds__(256, 3)
k_mega(const float* __restrict__ x, const void* __restrict__ cid, int n,
       const float* __restrict__ W1, const float* __restrict__ W2,
       const float* __restrict__ b1, const float* __restrict__ b2,
       const float* __restrict__ Wfc, const float* __restrict__ bfc,
       const float* __restrict__ Wa, const float* __restrict__ ba,
       const float* __restrict__ Wb, const float* __restrict__ bb,
       const float* __restrict__ Wcs, const float* __restrict__ bcs,
       const float* __restrict__ Wr, const float* __restrict__ br,
       const float* __restrict__ Wcls, const float* __restrict__ bcls,
       float* __restrict__ out, int out_size) {
    extern __shared__ char dsm[];
    __shared__ float s_col[128];
    __shared__ int s_task;
    int tid = threadIdx.x;

    int ng = g_ng;
    int tb0 = g_tb[0], tb1 = g_tb[1], tb2 = g_tb[2], tb3 = g_tb[3];
    int tb4 = g_tb[4], tb5 = g_tb[5], tb6 = g_tb[6], tb7 = g_tb[7];
    int ntask = g_ntask;

    for (;;) {
        if (tid == 0) s_task = atomicAdd(&g_task, 1);
        __syncthreads();
        int t = s_task;
        if (t >= ntask) break;

        if (t < tb0) {
            gather_task(x, cid, n, t * GROWS, dsm, tid);
        } else if (t < tb1) {                          // conv W1 (64 tiles/cluster)
            int tc = t - tb0;
            int c = tc >> 6, rem = tc & 63;
            conv_tile(W1 + (size_t)c * D_IN * D_H, g_W1t + (size_t)c * D_H * D_IN,
                      D_IN, D_H, (rem >> 2) * 64, (rem & 3) * 128, (float*)dsm, tid);
            __threadfence();
            __syncthreads();
            if (tid == 0) atomicAdd(&g_cw1c[c], 1);
        } else if (t < tb2) {                          // G1
            int t1 = t - tb1;
            int c = 0;
#pragma unroll
            for (int cc = 0; cc < C_CLUST; cc++) if (t1 >= g_g1s[cc + 1]) c = cc + 1;
            int rem = t1 - g_g1s[c];
            int mb = rem >> 2;
            int m0 = mb * MT, n0 = (rem & 3) * 128;
            if (tid == 0) {
                SPIN_WAIT(ldacq(&g_gather_done) < ng || ldacq(&g_cw1c[c]) < CW1_PER);
            }
            __syncthreads();
            gemm_tile<false>(g_Xg, g_W1t + (size_t)c * D_H * D_IN, b1 + c * D_H, nullptr,
                             D_IN, g_count[c], g_off[c], m0, n0, dsm, s_col, tid);
            __threadfence();
            __syncthreads();
            if (tid == 0) atomicAdd(&g_g1_mb[c * MBMAX + mb], 1);
        } else if (t < tb3) {                          // conv W2 (32 tiles/cluster)
            int tc = t - tb2;
            int c = tc >> 5, rem = tc & 31;
            conv_tile(W2 + (size_t)c * D_H * D_H, g_W2t + (size_t)c * D_H * D_H,
                      D_H, D_H, (rem >> 2) * 64, (rem & 3) * 128, (float*)dsm, tid);
            __threadfence();
            __syncthreads();
            if (tid == 0) atomicAdd(&g_cw2c[c], 1);
        } else if (t < tb4) {                          // G2 (fine-gated per 64-row m-block)
            int t2 = t - tb3;
            int c = 0;
#pragma unroll
            for (int cc = 0; cc < C_CLUST; cc++) if (t2 >= g_g2s[cc + 1]) c = cc + 1;
            int rem = t2 - g_g2s[c];
            int mb = rem >> 2;
            int m0 = mb * MT, n0 = (rem & 3) * 128;
            if (tid == 0) {
                SPIN_WAIT(ldacq(&g_g1_mb[c * MBMAX + mb]) < 4 || ldacq(&g_cw2c[c]) < CW2_PER);
            }
            __syncthreads();
            gemm_tile<true>(g_H1, g_W2t + (size_t)c * D_H * D_H, b2 + c * D_H,
                            g_pool + c * D_H, D_H, g_count[c], g_off[c], m0, n0, dsm, s_col, tid);
            __threadfence();
            __syncthreads();
            if (tid == 0) atomicAdd(&g_g2_done[c], 1);
        } else if (t < tb5) {                          // E1
            int idx = t - tb4;
            int c = idx >> 4, i = idx & 15;
            int target = g_g2s[c + 1] - g_g2s[c];
            if (tid == 0) { SPIN_WAIT(ldacq(&g_g2_done[c]) < target); }
            __syncthreads();
            e1_task(c, i, Wfc, bfc, dsm, tid);
        } else if (t < tb6) {                          // E2
            int idx = t - tb5;
            int c = idx >> 3, i = idx & 7;
            if (tid == 0) { SPIN_WAIT(ldacq(&g_e1c[c]) < 16); }
            __syncthreads();
            e2_task(c, i, Wa, ba, Wb, bb, Wcs, dsm, tid);
        } else if (t < tb7) {                          // E3
            if (tid == 0) { SPIN_WAIT(ldacq(&g_e2) < NE2T); }
            __syncthreads();
            e3_task(t - tb6, bcs, Wr, br, dsm, tid);
        } else {                                       // E4
            if (tid == 0) { SPIN_WAIT(ldacq(&g_e3) < NE3); }
            __syncthreads();
            e4_task(Wcls, bcls, out, out_size, dsm, tid);
        }
        __syncthreads();
    }
}

// ---------------- launch ----------------
extern "C" void kernel_launch(void* const* d_in, const int* in_sizes, int n_in,
                              void* d_out, int out_size) {
    const float* x    = (const float*)d_in[0];
    const void*  cid  = d_in[1];
    const float* W1   = (const float*)d_in[2];
    const float* b1   = (const float*)d_in[3];
    const float* W2   = (const float*)d_in[4];
    const float* b2   = (const float*)d_in[5];
    const float* Wfc  = (const float*)d_in[6];
    const float* bfc  = (const float*)d_in[7];
    const float* Wa   = (const float*)d_in[8];
    const float* ba   = (const float*)d_in[9];
    const float* Wb   = (const float*)d_in[10];
    const float* bb   = (const float*)d_in[11];
    const float* Wc_  = (const float*)d_in[12];
    const float* bc_  = (const float*)d_in[13];
    const float* Wr   = (const float*)d_in[14];
    const float* br   = (const float*)d_in[15];
    const float* Wcls = (const float*)d_in[16];
    const float* bcls = (const float*)d_in[17];

    int n = in_sizes[0] / D_IN;

    static int nsm = 0;
    if (!nsm) {
        cudaDeviceProp prop;
        cudaGetDeviceProperties(&prop, 0);
        nsm = prop.multiProcessorCount;
        cudaFuncSetAttribute(k_mega, cudaFuncAttributeMaxDynamicSharedMemorySize, SMEM_SZ);
    }

    k_reset<<<1, 512>>>();                                     // 1
    k_count<<<(n + 255) / 256, 256>>>(cid, n);                 // 2
    k_offsets<<<1, 32>>>(n);                                   // 3
    k_mega<<<3 * nsm, 256, SMEM_SZ>>>(                         // 4  <- ncu target
        x, cid, n, W1, W2, b1, b2, Wfc, bfc, Wa, ba, Wb, bb,
        Wc_, bc_, Wr, br, Wcls, bcls, (float*)d_out, out_size);
}